// round 7
// baseline (speedup 1.0000x reference)
#include <cuda_runtime.h>
#include <stdint.h>

#define N_NODES 50000
#define N_PAD   50048   // multiple of 128 for k_h2 tiling
#define N_EDGES 800000
#define HID     128
#define OUTC    64

// ---- scratch (device globals; no allocation allowed) ----
__device__ int   g_deg[N_NODES];
__device__ int   g_rowstart[N_NODES];
__device__ int   g_wpos[N_NODES];
__device__ int   g_csrc[N_EDGES];
__device__ int   g_total;
__device__ float g_dinv[N_NODES];
__device__ __align__(16) float g_v[N_PAD * 4];      // layer-1 aggregated 3-vec (pad stays 0)
__device__ __align__(16) float g_h2[N_PAD * OUTC];

#define PACK2(d, lo, hi) asm("mov.b64 %0, {%1, %2};" : "=l"(d) : "f"(lo), "f"(hi))
#define UNPACK2(lo, hi, s) asm("mov.b64 {%0, %1}, %2;" : "=f"(lo), "=f"(hi) : "l"(s))
#define FMA2(d, a, b, c) asm("fma.rn.f32x2 %0, %1, %2, %3;" : "=l"(d) : "l"(a), "l"(b), "l"(c))

// 1) zero degrees + cursor
__global__ void k_init() {
    int i = blockIdx.x * blockDim.x + threadIdx.x;
    if (i < N_NODES) g_deg[i] = 0;
    if (i == 0) g_total = 0;
}

// 2) degree histogram on dst; 8 edges/thread for MLP (self-loop folded as +1)
__global__ void k_deg(const int* __restrict__ ei) {
    int t = blockIdx.x * blockDim.x + threadIdx.x;
    if (t >= N_EDGES / 8) return;
    const int4* dp = (const int4*)(ei + N_EDGES);
    int4 d0 = dp[2 * t];
    int4 d1 = dp[2 * t + 1];
    atomicAdd(&g_deg[d0.x], 1);
    atomicAdd(&g_deg[d0.y], 1);
    atomicAdd(&g_deg[d0.z], 1);
    atomicAdd(&g_deg[d0.w], 1);
    atomicAdd(&g_deg[d1.x], 1);
    atomicAdd(&g_deg[d1.y], 1);
    atomicAdd(&g_deg[d1.z], 1);
    atomicAdd(&g_deg[d1.w], 1);
}

// 3) row allocation: warp-shuffle scan + one atomic per warp (order-free CSR rows)
__global__ void k_assign() {
    int i = blockIdx.x * blockDim.x + threadIdx.x;
    int lane = threadIdx.x & 31;
    int deg = (i < N_NODES) ? g_deg[i] : 0;
    int incl = deg;
    #pragma unroll
    for (int o = 1; o < 32; o <<= 1) {
        int v = __shfl_up_sync(0xffffffff, incl, o);
        if (lane >= o) incl += v;
    }
    int base = 0;
    if (lane == 31) base = atomicAdd(&g_total, incl);   // incl@31 = warp total
    base = __shfl_sync(0xffffffff, base, 31);
    if (i < N_NODES) {
        int rs = base + incl - deg;
        g_rowstart[i] = rs;
        g_wpos[i] = rs;
        g_dinv[i] = rsqrtf((float)(deg + 1));
    }
}

// 4) CSR scatter; 8 edges/thread: 8 independent ATOMG chains in flight
__global__ void k_csr(const int* __restrict__ ei) {
    int t = blockIdx.x * blockDim.x + threadIdx.x;
    if (t >= N_EDGES / 8) return;
    const int4* sp = (const int4*)ei;
    const int4* dp = (const int4*)(ei + N_EDGES);
    int4 s0 = sp[2 * t];
    int4 s1 = sp[2 * t + 1];
    int4 d0 = dp[2 * t];
    int4 d1 = dp[2 * t + 1];
    int p0 = atomicAdd(&g_wpos[d0.x], 1);
    int p1 = atomicAdd(&g_wpos[d0.y], 1);
    int p2 = atomicAdd(&g_wpos[d0.z], 1);
    int p3 = atomicAdd(&g_wpos[d0.w], 1);
    int p4 = atomicAdd(&g_wpos[d1.x], 1);
    int p5 = atomicAdd(&g_wpos[d1.y], 1);
    int p6 = atomicAdd(&g_wpos[d1.z], 1);
    int p7 = atomicAdd(&g_wpos[d1.w], 1);
    g_csrc[p0] = s0.x;
    g_csrc[p1] = s0.y;
    g_csrc[p2] = s0.z;
    g_csrc[p3] = s0.w;
    g_csrc[p4] = s1.x;
    g_csrc[p5] = s1.y;
    g_csrc[p6] = s1.z;
    g_csrc[p7] = s1.w;
}

// 5) layer-1 gather in 3-dim space: warp per node, atomic-free
__global__ void k_gather1(const float* __restrict__ x) {
    int gid = blockIdx.x * blockDim.x + threadIdx.x;
    int node = gid >> 5;
    int lane = gid & 31;
    if (node >= N_NODES) return;
    int row = g_rowstart[node];
    int end = row + g_deg[node];
    float a0 = 0.f, a1 = 0.f, a2 = 0.f;
    for (int e = row + lane; e < end; e += 32) {
        int s = g_csrc[e];
        float w = g_dinv[s];
        a0 = fmaf(__ldg(&x[s * 3 + 0]), w, a0);
        a1 = fmaf(__ldg(&x[s * 3 + 1]), w, a1);
        a2 = fmaf(__ldg(&x[s * 3 + 2]), w, a2);
    }
    #pragma unroll
    for (int o = 16; o > 0; o >>= 1) {
        a0 += __shfl_down_sync(0xffffffff, a0, o);
        a1 += __shfl_down_sync(0xffffffff, a1, o);
        a2 += __shfl_down_sync(0xffffffff, a2, o);
    }
    if (lane == 0) {
        float dd = g_dinv[node];
        float sl = dd * dd;
        float4 v;
        v.x = fmaf(dd, a0, sl * __ldg(&x[node * 3 + 0]));
        v.y = fmaf(dd, a1, sl * __ldg(&x[node * 3 + 1]));
        v.z = fmaf(dd, a2, sl * __ldg(&x[node * 3 + 2]));
        v.w = 0.f;
        ((float4*)g_v)[node] = v;
    }
}

// 6) fused h1 (relu(v@W1+b1), smem k-major) + h2 = h1 @ W2 with fma.rn.f32x2
//    128 nodes/block, 256 threads; thread = (8 nodes = 4 node-pairs, 4 cols).
__global__ void __launch_bounds__(256) k_h2(const float* __restrict__ W1,
                                            const float* __restrict__ b1,
                                            const float* __restrict__ W2) {
    __shared__ float4 sW2[HID * 16];    // [k][16 col-quads]       32 KB
    __shared__ float  sh1T[HID * 128];  // [k][node] transposed    64 KB
    int tid = threadIdx.x;
    int nodeBase = blockIdx.x * 128;

    #pragma unroll 4
    for (int i = tid; i < HID * 16; i += 256) sW2[i] = ((const float4*)W2)[i];

    #pragma unroll 4
    for (int i = tid; i < 128 * 32; i += 256) {
        int node = i & 127;
        int q    = i >> 7;
        float4 v  = ((const float4*)g_v)[nodeBase + node];
        float4 w0 = __ldg(&((const float4*)W1)[0 * 32 + q]);
        float4 w1 = __ldg(&((const float4*)W1)[1 * 32 + q]);
        float4 w2 = __ldg(&((const float4*)W1)[2 * 32 + q]);
        float4 bq = __ldg(&((const float4*)b1)[q]);
        sh1T[(4 * q + 0) * 128 + node] = fmaxf(fmaf(v.x, w0.x, fmaf(v.y, w1.x, fmaf(v.z, w2.x, bq.x))), 0.f);
        sh1T[(4 * q + 1) * 128 + node] = fmaxf(fmaf(v.x, w0.y, fmaf(v.y, w1.y, fmaf(v.z, w2.y, bq.y))), 0.f);
        sh1T[(4 * q + 2) * 128 + node] = fmaxf(fmaf(v.x, w0.z, fmaf(v.y, w1.z, fmaf(v.z, w2.z, bq.z))), 0.f);
        sh1T[(4 * q + 3) * 128 + node] = fmaxf(fmaf(v.x, w0.w, fmaf(v.y, w1.w, fmaf(v.z, w2.w, bq.w))), 0.f);
    }
    __syncthreads();

    int c  = tid & 15;        // cols 4c..4c+3
    int m0 = (tid >> 4) * 8;  // nodes m0..m0+7 (4 packed pairs)

    unsigned long long acc[4][4];
    #pragma unroll
    for (int p = 0; p < 4; p++)
        #pragma unroll
        for (int cc = 0; cc < 4; cc++) acc[p][cc] = 0ull;

    #pragma unroll 2
    for (int kb = 0; kb < HID; kb += 4) {
        #pragma unroll
        for (int kk = 0; kk < 4; kk++) {
            int k = kb + kk;
            float4 w = sW2[k * 16 + c];
            unsigned long long wp[4];
            PACK2(wp[0], w.x, w.x);
            PACK2(wp[1], w.y, w.y);
            PACK2(wp[2], w.z, w.z);
            PACK2(wp[3], w.w, w.w);
            float4 ha = *(const float4*)&sh1T[k * 128 + m0];
            float4 hb = *(const float4*)&sh1T[k * 128 + m0 + 4];
            unsigned long long hp[4];
            PACK2(hp[0], ha.x, ha.y);
            PACK2(hp[1], ha.z, ha.w);
            PACK2(hp[2], hb.x, hb.y);
            PACK2(hp[3], hb.z, hb.w);
            #pragma unroll
            for (int p = 0; p < 4; p++) {
                FMA2(acc[p][0], hp[p], wp[0], acc[p][0]);
                FMA2(acc[p][1], hp[p], wp[1], acc[p][1]);
                FMA2(acc[p][2], hp[p], wp[2], acc[p][2]);
                FMA2(acc[p][3], hp[p], wp[3], acc[p][3]);
            }
        }
    }

    #pragma unroll
    for (int p = 0; p < 4; p++) {
        float4 r0, r1;
        UNPACK2(r0.x, r1.x, acc[p][0]);
        UNPACK2(r0.y, r1.y, acc[p][1]);
        UNPACK2(r0.z, r1.z, acc[p][2]);
        UNPACK2(r0.w, r1.w, acc[p][3]);
        int n0 = nodeBase + m0 + 2 * p;
        ((float4*)g_h2)[(size_t)n0 * 16 + c] = r0;
        ((float4*)g_h2)[(size_t)(n0 + 1) * 16 + c] = r1;
    }
}

// 7) layer-2 gather, 16 threads/node (one float4 quad each), unroll x4
__global__ void k_gather2(const float* __restrict__ b2,
                          float* __restrict__ out) {
    int gid = blockIdx.x * blockDim.x + threadIdx.x;
    int node = gid >> 4;
    int q    = gid & 15;
    if (node >= N_NODES) return;
    int row = g_rowstart[node];
    int end = row + g_deg[node];
    float4 acc = make_float4(0.f, 0.f, 0.f, 0.f);
    int e = row;
    for (; e + 4 <= end; e += 4) {
        int s0 = g_csrc[e];
        int s1 = g_csrc[e + 1];
        int s2 = g_csrc[e + 2];
        int s3 = g_csrc[e + 3];
        float w0 = g_dinv[s0];
        float w1 = g_dinv[s1];
        float w2 = g_dinv[s2];
        float w3 = g_dinv[s3];
        float4 h0 = ((const float4*)g_h2)[(size_t)s0 * 16 + q];
        float4 h1 = ((const float4*)g_h2)[(size_t)s1 * 16 + q];
        float4 h2 = ((const float4*)g_h2)[(size_t)s2 * 16 + q];
        float4 h3 = ((const float4*)g_h2)[(size_t)s3 * 16 + q];
        acc.x = fmaf(w0, h0.x, fmaf(w1, h1.x, fmaf(w2, h2.x, fmaf(w3, h3.x, acc.x))));
        acc.y = fmaf(w0, h0.y, fmaf(w1, h1.y, fmaf(w2, h2.y, fmaf(w3, h3.y, acc.y))));
        acc.z = fmaf(w0, h0.z, fmaf(w1, h1.z, fmaf(w2, h2.z, fmaf(w3, h3.z, acc.z))));
        acc.w = fmaf(w0, h0.w, fmaf(w1, h1.w, fmaf(w2, h2.w, fmaf(w3, h3.w, acc.w))));
    }
    for (; e < end; e++) {
        int s = g_csrc[e];
        float w = g_dinv[s];
        float4 h = ((const float4*)g_h2)[(size_t)s * 16 + q];
        acc.x = fmaf(w, h.x, acc.x);
        acc.y = fmaf(w, h.y, acc.y);
        acc.z = fmaf(w, h.z, acc.z);
        acc.w = fmaf(w, h.w, acc.w);
    }
    float dd = g_dinv[node];
    float sl = dd * dd;
    float4 hs = ((const float4*)g_h2)[(size_t)node * 16 + q];
    float4 bb = __ldg(&((const float4*)b2)[q]);
    float4 o;
    o.x = fmaf(dd, acc.x, fmaf(sl, hs.x, bb.x));
    o.y = fmaf(dd, acc.y, fmaf(sl, hs.y, bb.y));
    o.z = fmaf(dd, acc.z, fmaf(sl, hs.z, bb.z));
    o.w = fmaf(dd, acc.w, fmaf(sl, hs.w, bb.w));
    ((float4*)out)[(size_t)node * 16 + q] = o;
}

extern "C" void kernel_launch(void* const* d_in, const int* in_sizes, int n_in,
                              void* d_out, int out_size) {
    const float* x  = (const float*)d_in[0];
    const int*   ei = (const int*)d_in[1];   // int64 in ref -> int32 on device (JAX x64 off)
    const float* W1 = (const float*)d_in[2];
    const float* b1 = (const float*)d_in[3];
    const float* W2 = (const float*)d_in[4];
    const float* b2 = (const float*)d_in[5];
    float* out = (float*)d_out;

    k_init<<<(N_NODES + 255) / 256, 256>>>();
    k_deg<<<(N_EDGES / 8 + 255) / 256, 256>>>(ei);
    k_assign<<<(N_NODES + 255) / 256, 256>>>();
    k_csr<<<(N_EDGES / 8 + 255) / 256, 256>>>(ei);
    k_gather1<<<(N_NODES * 32 + 255) / 256, 256>>>(x);
    k_h2<<<N_PAD / 128, 256>>>(W1, b1, W2);
    k_gather2<<<(N_NODES * 16 + 255) / 256, 256>>>(b2, out);
}